// round 9
// baseline (speedup 1.0000x reference)
#include <cuda_runtime.h>
#include <cuda_fp16.h>
#include <math.h>
#include <stdint.h>

typedef unsigned long long ull;

// Problem constants (fixed shapes)
#define NTOK   4096
#define NHEAD  8
#define NSAMP  27
#define CDIM   512
#define QKVW   1536

// -------- scratch (device globals; no allocations allowed) --------
__device__ float  g_qkv[NTOK * QKVW];          // fp32 qkv (N, 3C)
__device__ float  g_off[NHEAD * NTOK * 81];    // offsets per (h,n)
__device__ float  g_ao [NTOK * CDIM];          // attention output fp32
__device__ float  g_pos[3 * NHEAD * NTOK * 44];// precomputed pos-emb tables
__device__ __half g_vh [NTOK * CDIM];          // v in fp16 (N, 512)

// Packed fp32x2 FMA (Blackwell): d = a*b + d
#define FMA2(d, a, b) \
    asm("fma.rn.f32x2 %0, %1, %2, %0;" : "+l"(d) : "l"(a), "l"(b))
#define PACK2(d, s) \
    asm("mov.b64 %0, {%1, %1};" : "=l"(d) : "f"(s))

// ============================================================
// f32x2 SGEMM (NT): C[M,N] = A[M,K] @ W[N,K]^T (+ bias)
// (R7-proven core). If vh != nullptr, tiles with n0 >= 1024 also
// emit fp16 copies of their outputs (the v region of qkv).
// ============================================================
template<int BM>
__global__ void __launch_bounds__(256, 2) sgemm_f32x2(
    const float* __restrict__ A, const float* __restrict__ W,
    const float* __restrict__ bias, float* __restrict__ C,
    __half* __restrict__ vh, int N, int K)
{
    constexpr int MT  = BM / 16;
    constexpr int AL  = BM / 32;
    constexpr int TPR = 8 / AL;
    constexpr int SA  = BM + 4;

    __shared__ __align__(16) float As[2][8][SA];
    __shared__ __align__(16) float Ws[2][8][132];

    const int tid = threadIdx.x;
    const int tx = tid & 15;
    const int ty = tid >> 4;
    const int m0 = blockIdx.y * BM, n0 = blockIdx.x * 128;
    const int alr = tid / TPR;
    const int alk = (tid % TPR) * AL;
    const int wlr = tid >> 1, wlk = (tid & 1) * 4;

    const float* Ap = A + (size_t)(m0 + alr) * K + alk;
    const float* Wp = W + (size_t)(n0 + wlr) * K + wlk;

    ull acc[MT][4];
#pragma unroll
    for (int i = 0; i < MT; i++)
#pragma unroll
        for (int j = 0; j < 4; j++) acc[i][j] = 0ULL;

    float ar[AL]; float4 wv;
    if (AL == 4) {
        float4 t = *(const float4*)Ap;
        ar[0] = t.x; ar[1] = t.y; ar[2] = t.z; ar[3] = t.w;
    } else {
        float2 t = *(const float2*)Ap;
        ar[0] = t.x; ar[1] = t.y;
    }
    wv = *(const float4*)Wp;
    {
#pragma unroll
        for (int i = 0; i < AL; i++)
            As[0][alk + i][alr] = ar[i];
        Ws[0][wlk + 0][wlr] = wv.x; Ws[0][wlk + 1][wlr] = wv.y;
        Ws[0][wlk + 2][wlr] = wv.z; Ws[0][wlk + 3][wlr] = wv.w;
    }
    __syncthreads();

    const int nst = K >> 3;
    for (int st = 0; st < nst; st++) {
        const int buf = st & 1;
        const bool has = (st + 1) < nst;
        float ar2[AL]; float4 wv2;
        if (has) {
            if (AL == 4) {
                float4 t = *(const float4*)(Ap + (st + 1) * 8);
                ar2[0] = t.x; ar2[1] = t.y; ar2[2] = t.z; ar2[3] = t.w;
            } else {
                float2 t = *(const float2*)(Ap + (st + 1) * 8);
                ar2[0] = t.x; ar2[1] = t.y;
            }
            wv2 = *(const float4*)(Wp + (st + 1) * 8);
        }
#pragma unroll
        for (int kk = 0; kk < 8; kk++) {
            float af[MT];
            *(float4*)&af[0] = *(const float4*)&As[buf][kk][ty * MT];
            if (MT == 8)
                *(float4*)&af[4] = *(const float4*)&As[buf][kk][ty * MT + 4];
            ull a2[MT];
#pragma unroll
            for (int i = 0; i < MT; i++) PACK2(a2[i], af[i]);
            ulonglong2 q0 = *(const ulonglong2*)&Ws[buf][kk][tx * 8];
            ulonglong2 q1 = *(const ulonglong2*)&Ws[buf][kk][tx * 8 + 4];
            ull b2[4] = {q0.x, q0.y, q1.x, q1.y};
#pragma unroll
            for (int i = 0; i < MT; i++) {
                FMA2(acc[i][0], a2[i], b2[0]);
                FMA2(acc[i][1], a2[i], b2[1]);
                FMA2(acc[i][2], a2[i], b2[2]);
                FMA2(acc[i][3], a2[i], b2[3]);
            }
        }
        if (has) {
            const int nb = buf ^ 1;
#pragma unroll
            for (int i = 0; i < AL; i++)
                As[nb][alk + i][alr] = ar2[i];
            Ws[nb][wlk + 0][wlr] = wv2.x; Ws[nb][wlk + 1][wlr] = wv2.y;
            Ws[nb][wlk + 2][wlr] = wv2.z; Ws[nb][wlk + 3][wlr] = wv2.w;
        }
        __syncthreads();
    }

    float bv[8];
#pragma unroll
    for (int j = 0; j < 8; j++)
        bv[j] = bias ? __ldg(bias + n0 + tx * 8 + j) : 0.f;

    const bool emit_v = (vh != nullptr) && (n0 >= 1024);

#pragma unroll
    for (int i = 0; i < MT; i++) {
        union { ull u; float2 f; } p[4];
#pragma unroll
        for (int j = 0; j < 4; j++) p[j].u = acc[i][j];
        float4 o0, o1;
        o0.x = p[0].f.x + bv[0]; o0.y = p[0].f.y + bv[1];
        o0.z = p[1].f.x + bv[2]; o0.w = p[1].f.y + bv[3];
        o1.x = p[2].f.x + bv[4]; o1.y = p[2].f.y + bv[5];
        o1.z = p[3].f.x + bv[6]; o1.w = p[3].f.y + bv[7];
        const int row = m0 + ty * MT + i;
        float* cp = C + (size_t)row * N + n0 + tx * 8;
        *(float4*)cp = o0;
        *(float4*)(cp + 4) = o1;
        if (emit_v) {
            union { __half2 h2[4]; uint4 u; } hv;
            hv.h2[0] = __float22half2_rn(make_float2(o0.x, o0.y));
            hv.h2[1] = __float22half2_rn(make_float2(o0.z, o0.w));
            hv.h2[2] = __float22half2_rn(make_float2(o1.x, o1.y));
            hv.h2[3] = __float22half2_rn(make_float2(o1.z, o1.w));
            *(uint4*)(vh + (size_t)row * 512 + (n0 - 1024) + tx * 8) = hv.u;
        }
    }
}

// ============================================================
// Offsets: g_off[(h*N+n)*81 + c] = sum_k x[n, h*64+k] * w_off[c, k]
// ============================================================
__global__ void __launch_bounds__(256) offset_kernel(
    const float* __restrict__ x, const float* __restrict__ w_off)
{
    __shared__ float sw[81 * 64];
    const int tid = threadIdx.x;
    for (int i = tid; i < 81 * 64 / 4; i += 256)
        ((float4*)sw)[i] = ((const float4*)w_off)[i];
    __syncthreads();

    const int g = blockIdx.x * 256 + tid;
    const int h = g & 7, n = g >> 3;

    float4 xr[16];
    const float4* xp = (const float4*)(x + (size_t)n * CDIM + h * 64);
#pragma unroll
    for (int i = 0; i < 16; i++) xr[i] = xp[i];

    float* op = g_off + ((size_t)h * NTOK + n) * 81;
    for (int c = 0; c < 81; c++) {
        const float4* wp = (const float4*)(sw + c * 64);
        float acc = 0.f;
#pragma unroll
        for (int i = 0; i < 16; i++) {
            float4 w4 = wp[i];
            acc = fmaf(w4.x, xr[i].x, acc);
            acc = fmaf(w4.y, xr[i].y, acc);
            acc = fmaf(w4.z, xr[i].z, acc);
            acc = fmaf(w4.w, xr[i].w, acc);
        }
        op[c] = acc;
    }
}

// ============================================================
// Positional-embedding precompute:
//   g_pos[((tbl*8+h)*NTOK + n)*44 + j] = q(h,n,:) . rel_tbl[j,:]
// tbl: 0=w, 1=h, 2=d.  Thread per (h, n); rel tables in smem (broadcast).
// ============================================================
__global__ void __launch_bounds__(256) pos_kernel(
    const float* __restrict__ rel_d, const float* __restrict__ rel_h,
    const float* __restrict__ rel_w)
{
    __shared__ __align__(16) float srel[3 * 42 * 64];
    const int tid = threadIdx.x;
    {
        float4* s4 = (float4*)srel;
        const float4* rw4 = (const float4*)rel_w;
        const float4* rh4 = (const float4*)rel_h;
        const float4* rd4 = (const float4*)rel_d;
        for (int i = tid; i < 672; i += 256) {
            s4[i] = rw4[i];
            s4[672 + i] = rh4[i];
            s4[1344 + i] = rd4[i];
        }
    }
    __syncthreads();

    const int h = blockIdx.y;
    const int n = blockIdx.x * 256 + tid;

    float4 q[16];
    const float4* qp = (const float4*)(g_qkv + (size_t)n * QKVW + h * 64);
#pragma unroll
    for (int i = 0; i < 16; i++) q[i] = qp[i];

    for (int tbl = 0; tbl < 3; tbl++) {
        const float4* rl = (const float4*)(srel + tbl * 42 * 64);
        float* dst = g_pos + ((size_t)(tbl * 8 + h) * NTOK + n) * 44;
        for (int j4 = 0; j4 < 11; j4++) {
            float res[4];
#pragma unroll
            for (int jj = 0; jj < 4; jj++) {
                const int j = j4 * 4 + jj;
                float a = 0.f, b = 0.f, c = 0.f, d = 0.f;
                if (j < 42) {
                    const float4* rr = rl + j * 16;
#pragma unroll
                    for (int i = 0; i < 16; i++) {
                        float4 rv = rr[i];
                        a = fmaf(q[i].x, rv.x, a);
                        b = fmaf(q[i].y, rv.y, b);
                        c = fmaf(q[i].z, rv.z, c);
                        d = fmaf(q[i].w, rv.w, d);
                    }
                }
                res[jj] = (a + b) + (c + d);
            }
            float4 outv; outv.x = res[0]; outv.y = res[1];
            outv.z = res[2]; outv.w = res[3];
            *(float4*)(dst + j4 * 4) = outv;
        }
    }
}

// ============================================================
// Fused deformable attention.
// Phase 1 (lane-parallel): lane s<27 computes trilinear geometry
//   (8 weights, 8 k byte-offsets, 8 v byte-offsets) + the precomputed
//   pos-emb scalar -> 112B smem record.
// Phase 2: per-sample loop: uniform LDS of the record, k fp32 gather
//   (2 wf/corner), v fp16 gather (1 wf/corner), reduce, exp, accumulate.
// ============================================================
__device__ __forceinline__ void corner_setup(
    int z, int y, int x, int s, float soz, float soy, float sox,
    int idx[8], float w[8])
{
    const float pz = (float)(z + s / 9 - 1) + soz;
    const float py = (float)(y + (s / 3) % 3 - 1) + soy;
    const float px = (float)(x + s % 3 - 1) + sox;
    const float fz = floorf(pz), fy = floorf(py), fx = floorf(px);
    const float wz = pz - fz, wy = py - fy, wx = px - fx;
    const int iz = (int)fz, iy = (int)fy, ix = (int)fx;
    const int z0 = min(max(iz, 0), 15), z1 = min(max(iz + 1, 0), 15);
    const int y0 = min(max(iy, 0), 15), y1 = min(max(iy + 1, 0), 15);
    const int x0 = min(max(ix, 0), 15), x1 = min(max(ix + 1, 0), 15);
    const float wz0 = ((unsigned)iz < 16u) ? 1.f - wz : 0.f;
    const float wz1 = ((unsigned)(iz + 1) < 16u) ? wz : 0.f;
    const float wy0 = ((unsigned)iy < 16u) ? 1.f - wy : 0.f;
    const float wy1 = ((unsigned)(iy + 1) < 16u) ? wy : 0.f;
    const float wx0 = ((unsigned)ix < 16u) ? 1.f - wx : 0.f;
    const float wx1 = ((unsigned)(ix + 1) < 16u) ? wx : 0.f;
    idx[0] = (z0 * 16 + y0) * 16 + x0;  w[0] = wz0 * wy0 * wx0;
    idx[1] = (z0 * 16 + y0) * 16 + x1;  w[1] = wz0 * wy0 * wx1;
    idx[2] = (z0 * 16 + y1) * 16 + x0;  w[2] = wz0 * wy1 * wx0;
    idx[3] = (z0 * 16 + y1) * 16 + x1;  w[3] = wz0 * wy1 * wx1;
    idx[4] = (z1 * 16 + y0) * 16 + x0;  w[4] = wz1 * wy0 * wx0;
    idx[5] = (z1 * 16 + y0) * 16 + x1;  w[5] = wz1 * wy0 * wx1;
    idx[6] = (z1 * 16 + y1) * 16 + x0;  w[6] = wz1 * wy1 * wx0;
    idx[7] = (z1 * 16 + y1) * 16 + x1;  w[7] = wz1 * wy1 * wx1;
}

#define GREC 28   // floats per geometry record (112B)

__global__ void __launch_bounds__(256) attn_kernel()
{
    __shared__ __align__(16) float sgeo[8 * NSAMP * GREC];  // 24.2 KB
    const int tid = threadIdx.x;
    const int warp = tid >> 5;
    const int lane = tid & 31;
    const int n = blockIdx.x * 8 + warp;
    const int h = blockIdx.y;
    const int z = n >> 8, y = (n >> 4) & 15, x = n & 15;
    const int c0 = lane << 1;

    // ---- phase 1: lane-parallel geometry + pos ----
    float* grec = sgeo + warp * NSAMP * GREC;
    if (lane < NSAMP) {
        const float* offp = g_off + ((size_t)h * NTOK + n) * 81 + lane * 3;
        const float oz = offp[0], oy = offp[1], ox = offp[2];
        int idx[8]; float w[8];
        corner_setup(z, y, x, lane, oz, oy, ox, idx, w);
        const int j = 15 + lane - x;
        const int nzx = (z * 16 + x) * 16 + y;
        const int nxz = (x * 16 + z) * 16 + y;
        const float pos =
            g_pos[((size_t)h * NTOK + n) * 44 + j] +
            g_pos[((size_t)(8 + h) * NTOK + nzx) * 44 + j] +
            g_pos[((size_t)(16 + h) * NTOK + nxz) * 44 + j];
        float* r = grec + lane * GREC;
        *(float4*)(r + 0) = make_float4(w[0], w[1], w[2], w[3]);
        *(float4*)(r + 4) = make_float4(w[4], w[5], w[6], w[7]);
        int4 ka, kb4, va, vb4;
        ka.x  = idx[0] * (QKVW * 4); ka.y  = idx[1] * (QKVW * 4);
        ka.z  = idx[2] * (QKVW * 4); ka.w  = idx[3] * (QKVW * 4);
        kb4.x = idx[4] * (QKVW * 4); kb4.y = idx[5] * (QKVW * 4);
        kb4.z = idx[6] * (QKVW * 4); kb4.w = idx[7] * (QKVW * 4);
        va.x  = idx[0] * 1024; va.y  = idx[1] * 1024;
        va.z  = idx[2] * 1024; va.w  = idx[3] * 1024;
        vb4.x = idx[4] * 1024; vb4.y = idx[5] * 1024;
        vb4.z = idx[6] * 1024; vb4.w = idx[7] * 1024;
        *(int4*)(r + 8)  = ka;
        *(int4*)(r + 12) = kb4;
        *(int4*)(r + 16) = va;
        *(int4*)(r + 20) = vb4;
        r[24] = pos;
    }
    __syncwarp();

    // ---- phase 2: per-sample loop ----
    const float2 qa = *(const float2*)(g_qkv + (size_t)n * QKVW + h * 64 + c0);
    const char* kb = (const char*)(g_qkv + 512 + h * 64 + c0);
    const char* vbb = (const char*)g_vh + (h * 64 + c0) * 2;

    float ssum = 0.f, a0 = 0.f, a1 = 0.f;

#pragma unroll 3
    for (int s = 0; s < NSAMP; s++) {
        const float* r = grec + s * GREC;
        const float4 wa = *(const float4*)(r + 0);
        const float4 wb = *(const float4*)(r + 4);
        const int4   ka = *(const int4*)(r + 8);
        const int4   kc4 = *(const int4*)(r + 12);
        const int4   va = *(const int4*)(r + 16);
        const int4   vc4 = *(const int4*)(r + 20);
        const float pos = r[24];
        const float w[8] = {wa.x, wa.y, wa.z, wa.w, wb.x, wb.y, wb.z, wb.w};
        const int ko[8] = {ka.x, ka.y, ka.z, ka.w, kc4.x, kc4.y, kc4.z, kc4.w};
        const int vo[8] = {va.x, va.y, va.z, va.w, vc4.x, vc4.y, vc4.z, vc4.w};

        float2  kc[8];
        __half2 vc[8];
#pragma unroll
        for (int c = 0; c < 8; c++) {
            kc[c] = *(const float2*)(kb + ko[c]);
            vc[c] = *(const __half2*)(vbb + vo[c]);
        }

        float part = 0.f;
#pragma unroll
        for (int c = 0; c < 8; c++)
            part = fmaf(w[c], fmaf(kc[c].x, qa.x, kc[c].y * qa.y), part);

#pragma unroll
        for (int o = 16; o > 0; o >>= 1)
            part += __shfl_xor_sync(0xffffffffu, part, o);

        const float val = 0.125f * part + pos;
        const float pr = __expf(val);
        ssum += pr;

#pragma unroll
        for (int c = 0; c < 8; c++) {
            const float2 vf = __half22float2(vc[c]);
            const float pw = pr * w[c];
            a0 = fmaf(pw, vf.x, a0);
            a1 = fmaf(pw, vf.y, a1);
        }
    }

    const float inv = 1.f / ssum;
    float2 res; res.x = a0 * inv; res.y = a1 * inv;
    *(float2*)(g_ao + (size_t)n * CDIM + h * 64 + c0) = res;
}

// ============================================================
extern "C" void kernel_launch(void* const* d_in, const int* in_sizes, int n_in,
                              void* d_out, int out_size)
{
    const float* x      = (const float*)d_in[0];
    const float* w_qkv  = (const float*)d_in[1];
    const float* w_proj = (const float*)d_in[2];
    const float* b_proj = (const float*)d_in[3];
    const float* w_off  = (const float*)d_in[4];
    const float* rel_d  = (const float*)d_in[5];
    const float* rel_h  = (const float*)d_in[6];
    const float* rel_w  = (const float*)d_in[7];
    float* out = (float*)d_out;

    float *qkv_p, *ao_p;
    __half* vh_p;
    cudaGetSymbolAddress((void**)&qkv_p, g_qkv);
    cudaGetSymbolAddress((void**)&ao_p,  g_ao);
    cudaGetSymbolAddress((void**)&vh_p,  g_vh);

    // 1) per-head deformable offsets
    offset_kernel<<<NTOK * NHEAD / 256, 256>>>(x, w_off);

    // 2) qkv = x @ w_qkv^T (M=4096, N=1536, K=512); v tiles also emit fp16
    sgemm_f32x2<128><<<dim3(QKVW / 128, NTOK / 128), 256>>>(
        x, w_qkv, nullptr, qkv_p, vh_p, QKVW, CDIM);

    // 3) positional-embedding precompute
    pos_kernel<<<dim3(NTOK / 256, NHEAD), 256>>>(rel_d, rel_h, rel_w);

    // 4) fused deformable attention (ncu captures this launch)
    attn_kernel<<<dim3(NTOK / 8, NHEAD), 256>>>();

    // 5) out = attn_out @ w_proj^T + b_proj  (M=4096, N=512)
    sgemm_f32x2<64><<<dim3(CDIM / 128, NTOK / 64), 256>>>(
        ao_p, w_proj, b_proj, out, nullptr, CDIM, CDIM);
}

// round 10
// speedup vs baseline: 1.0436x; 1.0436x over previous
#include <cuda_runtime.h>
#include <cuda_fp16.h>
#include <math.h>
#include <stdint.h>

typedef unsigned long long ull;

// Problem constants (fixed shapes)
#define NTOK   4096
#define NHEAD  8
#define NSAMP  27
#define CDIM   512
#define QKVW   1536

// -------- scratch (device globals; no allocations allowed) --------
// g_qkv row layout (6144 B): q fp32 [0,2048) | k fp16 [4096,5120) | v fp16 [5120,6144)
// (bytes [2048,4096) unused)
__device__ float  g_qkv[NTOK * QKVW];
__device__ float  g_off[NHEAD * NTOK * 81];      // offsets per (h,n)
__device__ float  g_ao [NTOK * CDIM];            // attention output fp32
__device__ float  g_pos[3 * NHEAD * NTOK * 44];  // precomputed pos-emb tables

// Packed fp32x2 FMA (Blackwell): d = a*b + d
#define FMA2(d, a, b) \
    asm("fma.rn.f32x2 %0, %1, %2, %0;" : "+l"(d) : "l"(a), "l"(b))
#define PACK2(d, s) \
    asm("mov.b64 %0, {%1, %1};" : "=l"(d) : "f"(s))

// ============================================================
// f32x2 SGEMM (NT): C[M,N] = A[M,K] @ W[N,K]^T (+ bias)
// (R7-proven core). emit16 mode (qkv): tiles with n0 >= 512 store
// ONLY fp16 into the packed k/v region at row-byte 4096+(col-512)*2.
// ============================================================
template<int BM>
__global__ void __launch_bounds__(256, 2) sgemm_f32x2(
    const float* __restrict__ A, const float* __restrict__ W,
    const float* __restrict__ bias, float* __restrict__ C,
    int N, int K, int emit16)
{
    constexpr int MT  = BM / 16;
    constexpr int AL  = BM / 32;
    constexpr int TPR = 8 / AL;
    constexpr int SA  = BM + 4;

    __shared__ __align__(16) float As[2][8][SA];
    __shared__ __align__(16) float Ws[2][8][132];

    const int tid = threadIdx.x;
    const int tx = tid & 15;
    const int ty = tid >> 4;
    const int m0 = blockIdx.y * BM, n0 = blockIdx.x * 128;
    const int alr = tid / TPR;
    const int alk = (tid % TPR) * AL;
    const int wlr = tid >> 1, wlk = (tid & 1) * 4;

    const float* Ap = A + (size_t)(m0 + alr) * K + alk;
    const float* Wp = W + (size_t)(n0 + wlr) * K + wlk;

    ull acc[MT][4];
#pragma unroll
    for (int i = 0; i < MT; i++)
#pragma unroll
        for (int j = 0; j < 4; j++) acc[i][j] = 0ULL;

    float ar[AL]; float4 wv;
    if (AL == 4) {
        float4 t = *(const float4*)Ap;
        ar[0] = t.x; ar[1] = t.y; ar[2] = t.z; ar[3] = t.w;
    } else {
        float2 t = *(const float2*)Ap;
        ar[0] = t.x; ar[1] = t.y;
    }
    wv = *(const float4*)Wp;
    {
#pragma unroll
        for (int i = 0; i < AL; i++)
            As[0][alk + i][alr] = ar[i];
        Ws[0][wlk + 0][wlr] = wv.x; Ws[0][wlk + 1][wlr] = wv.y;
        Ws[0][wlk + 2][wlr] = wv.z; Ws[0][wlk + 3][wlr] = wv.w;
    }
    __syncthreads();

    const int nst = K >> 3;
    for (int st = 0; st < nst; st++) {
        const int buf = st & 1;
        const bool has = (st + 1) < nst;
        float ar2[AL]; float4 wv2;
        if (has) {
            if (AL == 4) {
                float4 t = *(const float4*)(Ap + (st + 1) * 8);
                ar2[0] = t.x; ar2[1] = t.y; ar2[2] = t.z; ar2[3] = t.w;
            } else {
                float2 t = *(const float2*)(Ap + (st + 1) * 8);
                ar2[0] = t.x; ar2[1] = t.y;
            }
            wv2 = *(const float4*)(Wp + (st + 1) * 8);
        }
#pragma unroll
        for (int kk = 0; kk < 8; kk++) {
            float af[MT];
            *(float4*)&af[0] = *(const float4*)&As[buf][kk][ty * MT];
            if (MT == 8)
                *(float4*)&af[4] = *(const float4*)&As[buf][kk][ty * MT + 4];
            ull a2[MT];
#pragma unroll
            for (int i = 0; i < MT; i++) PACK2(a2[i], af[i]);
            ulonglong2 q0 = *(const ulonglong2*)&Ws[buf][kk][tx * 8];
            ulonglong2 q1 = *(const ulonglong2*)&Ws[buf][kk][tx * 8 + 4];
            ull b2[4] = {q0.x, q0.y, q1.x, q1.y};
#pragma unroll
            for (int i = 0; i < MT; i++) {
                FMA2(acc[i][0], a2[i], b2[0]);
                FMA2(acc[i][1], a2[i], b2[1]);
                FMA2(acc[i][2], a2[i], b2[2]);
                FMA2(acc[i][3], a2[i], b2[3]);
            }
        }
        if (has) {
            const int nb = buf ^ 1;
#pragma unroll
            for (int i = 0; i < AL; i++)
                As[nb][alk + i][alr] = ar2[i];
            Ws[nb][wlk + 0][wlr] = wv2.x; Ws[nb][wlk + 1][wlr] = wv2.y;
            Ws[nb][wlk + 2][wlr] = wv2.z; Ws[nb][wlk + 3][wlr] = wv2.w;
        }
        __syncthreads();
    }

    float bv[8];
#pragma unroll
    for (int j = 0; j < 8; j++)
        bv[j] = bias ? __ldg(bias + n0 + tx * 8 + j) : 0.f;

    const bool half_out = emit16 && (n0 >= 512);

#pragma unroll
    for (int i = 0; i < MT; i++) {
        union { ull u; float2 f; } p[4];
#pragma unroll
        for (int j = 0; j < 4; j++) p[j].u = acc[i][j];
        float4 o0, o1;
        o0.x = p[0].f.x + bv[0]; o0.y = p[0].f.y + bv[1];
        o0.z = p[1].f.x + bv[2]; o0.w = p[1].f.y + bv[3];
        o1.x = p[2].f.x + bv[4]; o1.y = p[2].f.y + bv[5];
        o1.z = p[3].f.x + bv[6]; o1.w = p[3].f.y + bv[7];
        const int row = m0 + ty * MT + i;
        if (!half_out) {
            float* cp = C + (size_t)row * N + n0 + tx * 8;
            *(float4*)cp = o0;
            *(float4*)(cp + 4) = o1;
        } else {
            union { __half2 h2[4]; uint4 u; } hv;
            hv.h2[0] = __float22half2_rn(make_float2(o0.x, o0.y));
            hv.h2[1] = __float22half2_rn(make_float2(o0.z, o0.w));
            hv.h2[2] = __float22half2_rn(make_float2(o1.x, o1.y));
            hv.h2[3] = __float22half2_rn(make_float2(o1.z, o1.w));
            char* rowb = (char*)C + (size_t)row * (N * 4);
            *(uint4*)(rowb + 4096 + ((n0 - 512) + tx * 8) * 2) = hv.u;
        }
    }
}

// ============================================================
// Offsets: g_off[(h*N+n)*81 + c] = sum_k x[n, h*64+k] * w_off[c, k]
// ============================================================
__global__ void __launch_bounds__(256) offset_kernel(
    const float* __restrict__ x, const float* __restrict__ w_off)
{
    __shared__ float sw[81 * 64];
    const int tid = threadIdx.x;
    for (int i = tid; i < 81 * 64 / 4; i += 256)
        ((float4*)sw)[i] = ((const float4*)w_off)[i];
    __syncthreads();

    const int g = blockIdx.x * 256 + tid;
    const int h = g & 7, n = g >> 3;

    float4 xr[16];
    const float4* xp = (const float4*)(x + (size_t)n * CDIM + h * 64);
#pragma unroll
    for (int i = 0; i < 16; i++) xr[i] = xp[i];

    float* op = g_off + ((size_t)h * NTOK + n) * 81;
    for (int c = 0; c < 81; c++) {
        const float4* wp = (const float4*)(sw + c * 64);
        float acc = 0.f;
#pragma unroll
        for (int i = 0; i < 16; i++) {
            float4 w4 = wp[i];
            acc = fmaf(w4.x, xr[i].x, acc);
            acc = fmaf(w4.y, xr[i].y, acc);
            acc = fmaf(w4.z, xr[i].z, acc);
            acc = fmaf(w4.w, xr[i].w, acc);
        }
        op[c] = acc;
    }
}

// spacer launches (ncu captures the 4th launch -> qkv GEMM this round)
__device__ float g_dummy[1];
__global__ void dummy_kernel() { if (threadIdx.x == 0) g_dummy[0] = 1.f; }

// ============================================================
// Positional-embedding precompute:
//   g_pos[((tbl*8+h)*NTOK + n)*44 + j] = q(h,n,:) . rel_tbl[j,:]
// ============================================================
__global__ void __launch_bounds__(256) pos_kernel(
    const float* __restrict__ rel_d, const float* __restrict__ rel_h,
    const float* __restrict__ rel_w)
{
    __shared__ __align__(16) float srel[3 * 42 * 64];
    const int tid = threadIdx.x;
    {
        float4* s4 = (float4*)srel;
        const float4* rw4 = (const float4*)rel_w;
        const float4* rh4 = (const float4*)rel_h;
        const float4* rd4 = (const float4*)rel_d;
        for (int i = tid; i < 672; i += 256) {
            s4[i] = rw4[i];
            s4[672 + i] = rh4[i];
            s4[1344 + i] = rd4[i];
        }
    }
    __syncthreads();

    const int h = blockIdx.y;
    const int n = blockIdx.x * 256 + tid;

    float4 q[16];
    const float4* qp = (const float4*)(g_qkv + (size_t)n * QKVW + h * 64);
#pragma unroll
    for (int i = 0; i < 16; i++) q[i] = qp[i];

    for (int tbl = 0; tbl < 3; tbl++) {
        const float4* rl = (const float4*)(srel + tbl * 42 * 64);
        float* dst = g_pos + ((size_t)(tbl * 8 + h) * NTOK + n) * 44;
        for (int j4 = 0; j4 < 11; j4++) {
            float res[4];
#pragma unroll
            for (int jj = 0; jj < 4; jj++) {
                const int j = j4 * 4 + jj;
                float a = 0.f, b = 0.f, c = 0.f, d = 0.f;
                if (j < 42) {
                    const float4* rr = rl + j * 16;
#pragma unroll
                    for (int i = 0; i < 16; i++) {
                        float4 rv = rr[i];
                        a = fmaf(q[i].x, rv.x, a);
                        b = fmaf(q[i].y, rv.y, b);
                        c = fmaf(q[i].z, rv.z, c);
                        d = fmaf(q[i].w, rv.w, d);
                    }
                }
                res[jj] = (a + b) + (c + d);
            }
            float4 outv; outv.x = res[0]; outv.y = res[1];
            outv.z = res[2]; outv.w = res[3];
            *(float4*)(dst + j4 * 4) = outv;
        }
    }
}

// ============================================================
// Fused deformable attention (fp16 k+v packed in qkv rows).
// Phase 1: lane s<27 computes geometry (8 weights + 8 row byte-offsets)
//   + pos scalar -> 80B smem record.
// Phase 2: per sample, ONE pointer per corner; k via LDG[p], v via
//   LDG[p+1024] (immediate). 1 wavefront per corner per array.
// ============================================================
__device__ __forceinline__ void corner_setup(
    int z, int y, int x, int s, float soz, float soy, float sox,
    int idx[8], float w[8])
{
    const float pz = (float)(z + s / 9 - 1) + soz;
    const float py = (float)(y + (s / 3) % 3 - 1) + soy;
    const float px = (float)(x + s % 3 - 1) + sox;
    const float fz = floorf(pz), fy = floorf(py), fx = floorf(px);
    const float wz = pz - fz, wy = py - fy, wx = px - fx;
    const int iz = (int)fz, iy = (int)fy, ix = (int)fx;
    const int z0 = min(max(iz, 0), 15), z1 = min(max(iz + 1, 0), 15);
    const int y0 = min(max(iy, 0), 15), y1 = min(max(iy + 1, 0), 15);
    const int x0 = min(max(ix, 0), 15), x1 = min(max(ix + 1, 0), 15);
    const float wz0 = ((unsigned)iz < 16u) ? 1.f - wz : 0.f;
    const float wz1 = ((unsigned)(iz + 1) < 16u) ? wz : 0.f;
    const float wy0 = ((unsigned)iy < 16u) ? 1.f - wy : 0.f;
    const float wy1 = ((unsigned)(iy + 1) < 16u) ? wy : 0.f;
    const float wx0 = ((unsigned)ix < 16u) ? 1.f - wx : 0.f;
    const float wx1 = ((unsigned)(ix + 1) < 16u) ? wx : 0.f;
    idx[0] = (z0 * 16 + y0) * 16 + x0;  w[0] = wz0 * wy0 * wx0;
    idx[1] = (z0 * 16 + y0) * 16 + x1;  w[1] = wz0 * wy0 * wx1;
    idx[2] = (z0 * 16 + y1) * 16 + x0;  w[2] = wz0 * wy1 * wx0;
    idx[3] = (z0 * 16 + y1) * 16 + x1;  w[3] = wz0 * wy1 * wx1;
    idx[4] = (z1 * 16 + y0) * 16 + x0;  w[4] = wz1 * wy0 * wx0;
    idx[5] = (z1 * 16 + y0) * 16 + x1;  w[5] = wz1 * wy0 * wx1;
    idx[6] = (z1 * 16 + y1) * 16 + x0;  w[6] = wz1 * wy1 * wx0;
    idx[7] = (z1 * 16 + y1) * 16 + x1;  w[7] = wz1 * wy1 * wx1;
}

#define GREC 20   // floats per geometry record (80B)

__global__ void __launch_bounds__(256) attn_kernel()
{
    __shared__ __align__(16) float sgeo[8 * NSAMP * GREC];  // 17.3 KB
    const int tid = threadIdx.x;
    const int warp = tid >> 5;
    const int lane = tid & 31;
    const int n = blockIdx.x * 8 + warp;
    const int h = blockIdx.y;
    const int z = n >> 8, y = (n >> 4) & 15, x = n & 15;
    const int c0 = lane << 1;

    // ---- phase 1: lane-parallel geometry + pos ----
    float* grec = sgeo + warp * NSAMP * GREC;
    if (lane < NSAMP) {
        const float* offp = g_off + ((size_t)h * NTOK + n) * 81 + lane * 3;
        const float oz = offp[0], oy = offp[1], ox = offp[2];
        int idx[8]; float w[8];
        corner_setup(z, y, x, lane, oz, oy, ox, idx, w);
        const int j = 15 + lane - x;
        const int nzx = (z * 16 + x) * 16 + y;
        const int nxz = (x * 16 + z) * 16 + y;
        const float pos =
            g_pos[((size_t)h * NTOK + n) * 44 + j] +
            g_pos[((size_t)(8 + h) * NTOK + nzx) * 44 + j] +
            g_pos[((size_t)(16 + h) * NTOK + nxz) * 44 + j];
        float* r = grec + lane * GREC;
        *(float4*)(r + 0) = make_float4(w[0], w[1], w[2], w[3]);
        *(float4*)(r + 4) = make_float4(w[4], w[5], w[6], w[7]);
        int4 ka, kb4;
        ka.x  = idx[0] * 6144; ka.y  = idx[1] * 6144;
        ka.z  = idx[2] * 6144; ka.w  = idx[3] * 6144;
        kb4.x = idx[4] * 6144; kb4.y = idx[5] * 6144;
        kb4.z = idx[6] * 6144; kb4.w = idx[7] * 6144;
        *(int4*)(r + 8)  = ka;
        *(int4*)(r + 12) = kb4;
        r[16] = pos;
    }
    __syncwarp();

    // ---- phase 2: per-sample loop ----
    const float2 qa = *(const float2*)(g_qkv + (size_t)n * QKVW + h * 64 + c0);
    // lane base: k fp16 at row-byte 4096 + kcol*2; v at +1024
    const char* kbase = (const char*)g_qkv + 4096 + (h * 64 + c0) * 2;

    float ssum = 0.f, a0 = 0.f, a1 = 0.f;

#pragma unroll 3
    for (int s = 0; s < NSAMP; s++) {
        const float* r = grec + s * GREC;
        const float4 wa = *(const float4*)(r + 0);
        const float4 wb = *(const float4*)(r + 4);
        const int4   ka = *(const int4*)(r + 8);
        const int4   kc4 = *(const int4*)(r + 12);
        const float pos = r[16];
        const float w[8] = {wa.x, wa.y, wa.z, wa.w, wb.x, wb.y, wb.z, wb.w};
        const int ko[8] = {ka.x, ka.y, ka.z, ka.w, kc4.x, kc4.y, kc4.z, kc4.w};

        __half2 kh[8], vh[8];
#pragma unroll
        for (int c = 0; c < 8; c++) {
            const char* p = kbase + ko[c];
            kh[c] = *(const __half2*)p;
            vh[c] = *(const __half2*)(p + 1024);
        }

        float part = 0.f;
#pragma unroll
        for (int c = 0; c < 8; c++) {
            const float2 kf = __half22float2(kh[c]);
            part = fmaf(w[c], fmaf(kf.x, qa.x, kf.y * qa.y), part);
        }

#pragma unroll
        for (int o = 16; o > 0; o >>= 1)
            part += __shfl_xor_sync(0xffffffffu, part, o);

        const float val = 0.125f * part + pos;
        const float pr = __expf(val);
        ssum += pr;

#pragma unroll
        for (int c = 0; c < 8; c++) {
            const float2 vf = __half22float2(vh[c]);
            const float pw = pr * w[c];
            a0 = fmaf(pw, vf.x, a0);
            a1 = fmaf(pw, vf.y, a1);
        }
    }

    const float inv = 1.f / ssum;
    float2 res; res.x = a0 * inv; res.y = a1 * inv;
    *(float2*)(g_ao + (size_t)n * CDIM + h * 64 + c0) = res;
}

// ============================================================
extern "C" void kernel_launch(void* const* d_in, const int* in_sizes, int n_in,
                              void* d_out, int out_size)
{
    const float* x      = (const float*)d_in[0];
    const float* w_qkv  = (const float*)d_in[1];
    const float* w_proj = (const float*)d_in[2];
    const float* b_proj = (const float*)d_in[3];
    const float* w_off  = (const float*)d_in[4];
    const float* rel_d  = (const float*)d_in[5];
    const float* rel_h  = (const float*)d_in[6];
    const float* rel_w  = (const float*)d_in[7];
    float* out = (float*)d_out;

    float *qkv_p, *ao_p;
    cudaGetSymbolAddress((void**)&qkv_p, g_qkv);
    cudaGetSymbolAddress((void**)&ao_p,  g_ao);

    // 1) per-head deformable offsets
    offset_kernel<<<NTOK * NHEAD / 256, 256>>>(x, w_off);

    // 2,3) spacers (ncu captures launch #4 -> the qkv GEMM)
    dummy_kernel<<<1, 32>>>();
    dummy_kernel<<<1, 32>>>();

    // 4) qkv = x @ w_qkv^T; q fp32, k/v packed fp16 (emit16=1)
    sgemm_f32x2<128><<<dim3(QKVW / 128, NTOK / 128), 256>>>(
        x, w_qkv, nullptr, qkv_p, QKVW, CDIM, 1);

    // 5) positional-embedding precompute
    pos_kernel<<<dim3(NTOK / 256, NHEAD), 256>>>(rel_d, rel_h, rel_w);

    // 6) fused deformable attention
    attn_kernel<<<dim3(NTOK / 8, NHEAD), 256>>>();

    // 7) out = attn_out @ w_proj^T + b_proj
    sgemm_f32x2<64><<<dim3(CDIM / 128, NTOK / 64), 256>>>(
        ao_p, w_proj, b_proj, out, CDIM, CDIM, 0);
}